// round 2
// baseline (speedup 1.0000x reference)
#include <cuda_runtime.h>
#include <cstddef>

#define Nn   100000
#define Ee   256000
#define EMB  300
#define EMB2 600
#define LAYERS 5

// ---------------- device scratch (allocation-free rule: __device__ globals) ----------
__device__ float  g_hbufA[(size_t)Nn * EMB];   // 120 MB
__device__ float  g_hbufB[(size_t)Nn * EMB];   // 120 MB
__device__ float  g_agg  [(size_t)Nn * EMB];   // 120 MB
__device__ float  g_z1   [(size_t)Nn * EMB2];  // 240 MB
__device__ float  g_z2   [(size_t)Nn * EMB];   // 120 MB
__device__ float  g_etab [9 * EMB];
__device__ double g_sum  [EMB2];
__device__ double g_sq   [EMB2];
__device__ float  g_sc1  [EMB2];
__device__ float  g_sh1  [EMB2];
__device__ float  g_sc2  [EMB];
__device__ float  g_sh2  [EMB];

// ---------------- kernels -----------------------------------------------------------

// etab[c][k] = W_bond[l][k][c/3] + W_bond[l][k][6 + c%3], c = ea0*3+ea1 (ea in {0,1,2})
__global__ void build_etab(const float* __restrict__ Wb) {
    int c = blockIdx.x;
    int k = threadIdx.x;
    if (k < EMB) {
        int t0 = c / 3;
        int t1 = 6 + (c % 3);
        g_etab[c * EMB + k] = Wb[k * 9 + t0] + Wb[k * 9 + t1];
    }
}

// agg = (1 + eps[l]) * h
__global__ void agg_init(const float* __restrict__ h, const float* __restrict__ eps, int l) {
    int i = blockIdx.x * blockDim.x + threadIdx.x;
    if (i < Nn * EMB) {
        float ep = 1.0f + __ldg(eps + l);
        g_agg[i] = ep * h[i];
    }
}

// per-edge: msg = relu(h[src] + etab[combo]); atomicAdd into agg[dst]
__global__ void edge_msg(const float* __restrict__ h,
                         const int* __restrict__ ei,
                         const int* __restrict__ ea) {
    __shared__ float s_et[9 * EMB];
    for (int i = threadIdx.x; i < 9 * EMB; i += blockDim.x) s_et[i] = g_etab[i];
    __syncthreads();

    int warp = threadIdx.x >> 5;
    int lane = threadIdx.x & 31;
    int e = blockIdx.x * 8 + warp;
    if (e >= Ee) return;

    int src = ei[e];
    int dst = ei[Ee + e];
    int c   = ea[2 * e] * 3 + ea[2 * e + 1];

    const float* hr = h + (size_t)src * EMB;
    float*       ar = g_agg + (size_t)dst * EMB;
    const float* er = s_et + c * EMB;

    for (int k = lane; k < EMB; k += 32) {
        float v = hr[k] + er[k];
        if (v > 0.0f) atomicAdd(ar + k, v);   // relu: skip zero contributions
    }
}

// C[m][n] = sum_k f(A[m][k]) * B[n][k] + bias[n]
// TRANS=1: f(x) = relu(sc[k]*x + sh[k])  (BN1 + relu fused into GEMM2's A read)
template <int TRANS>
__global__ void __launch_bounds__(256)
gemm_tn(const float* __restrict__ A, const float* __restrict__ B,
        const float* __restrict__ bias,
        const float* __restrict__ sc, const float* __restrict__ sh,
        float* __restrict__ C, int M, int NC, int K) {
    __shared__ float As[16][132];
    __shared__ float Bs[16][68];

    int tid = threadIdx.x;
    int tx = tid & 15;       // 0..15 -> 4 cols each
    int ty = tid >> 4;       // 0..15 -> 8 rows each
    int m0 = blockIdx.x * 128;
    int n0 = blockIdx.y * 64;

    float acc[8][4];
#pragma unroll
    for (int i = 0; i < 8; i++)
#pragma unroll
        for (int j = 0; j < 4; j++) acc[i][j] = 0.0f;

    for (int k0 = 0; k0 < K; k0 += 16) {
        // --- load A tile 128x16 (2 float4 per thread), transform + transpose to As[k][m]
#pragma unroll
        for (int r = 0; r < 2; r++) {
            int idx = tid + r * 256;
            int m  = idx >> 2;
            int kk = (idx & 3) * 4;
            int gm = m0 + m;
            int gk = k0 + kk;
            float4 v = make_float4(0.f, 0.f, 0.f, 0.f);
            if (gm < M && gk < K) {
                v = *reinterpret_cast<const float4*>(A + (size_t)gm * K + gk);
                if (TRANS) {
                    v.x = fmaxf(fmaf(sc[gk + 0], v.x, sh[gk + 0]), 0.f);
                    v.y = fmaxf(fmaf(sc[gk + 1], v.y, sh[gk + 1]), 0.f);
                    v.z = fmaxf(fmaf(sc[gk + 2], v.z, sh[gk + 2]), 0.f);
                    v.w = fmaxf(fmaf(sc[gk + 3], v.w, sh[gk + 3]), 0.f);
                }
            }
            As[kk + 0][m] = v.x;
            As[kk + 1][m] = v.y;
            As[kk + 2][m] = v.z;
            As[kk + 3][m] = v.w;
        }
        // --- load B tile 64x16 (1 float4 per thread), transpose to Bs[k][n]
        {
            int n  = tid >> 2;
            int kk = (tid & 3) * 4;
            int gn = n0 + n;
            int gk = k0 + kk;
            float4 v = make_float4(0.f, 0.f, 0.f, 0.f);
            if (gn < NC && gk < K)
                v = *reinterpret_cast<const float4*>(B + (size_t)gn * K + gk);
            Bs[kk + 0][n] = v.x;
            Bs[kk + 1][n] = v.y;
            Bs[kk + 2][n] = v.z;
            Bs[kk + 3][n] = v.w;
        }
        __syncthreads();

#pragma unroll
        for (int kk = 0; kk < 16; kk++) {
            float a[8], b[4];
#pragma unroll
            for (int i = 0; i < 8; i++) a[i] = As[kk][ty * 8 + i];
#pragma unroll
            for (int j = 0; j < 4; j++) b[j] = Bs[kk][tx * 4 + j];
#pragma unroll
            for (int i = 0; i < 8; i++)
#pragma unroll
                for (int j = 0; j < 4; j++)
                    acc[i][j] = fmaf(a[i], b[j], acc[i][j]);
        }
        __syncthreads();
    }

    // --- store with bias
#pragma unroll
    for (int i = 0; i < 8; i++) {
        int gm = m0 + ty * 8 + i;
        if (gm >= M) continue;
        int gn = n0 + tx * 4;
        if (gn + 3 < NC) {
            float4 o;
            o.x = acc[i][0] + bias[gn + 0];
            o.y = acc[i][1] + bias[gn + 1];
            o.z = acc[i][2] + bias[gn + 2];
            o.w = acc[i][3] + bias[gn + 3];
            *reinterpret_cast<float4*>(C + (size_t)gm * NC + gn) = o;
        } else {
#pragma unroll
            for (int j = 0; j < 4; j++)
                if (gn + j < NC) C[(size_t)gm * NC + gn + j] = acc[i][j] + bias[gn + j];
        }
    }
}

__global__ void zero_stats(int C) {
    int i = blockIdx.x * blockDim.x + threadIdx.x;
    if (i < C) { g_sum[i] = 0.0; g_sq[i] = 0.0; }
}

// column-wise sum / sum-of-squares over M rows (fp32 partials, fp64 atomics)
__global__ void stats_kernel(const float* __restrict__ Z, int M, int C) {
    int col = blockIdx.x * blockDim.x + threadIdx.x;
    if (col >= C) return;
    int nchunk = gridDim.y;
    int chunk = (M + nchunk - 1) / nchunk;
    int r0 = blockIdx.y * chunk;
    int r1 = min(M, r0 + chunk);
    float s = 0.f, q = 0.f;
    for (int r = r0; r < r1; r++) {
        float v = Z[(size_t)r * C + col];
        s += v;
        q += v * v;
    }
    atomicAdd(&g_sum[col], (double)s);
    atomicAdd(&g_sq[col], (double)q);
}

// sc = gamma * rsqrt(var + eps); sh = beta - sc*mean
__global__ void bn_finalize(const float* __restrict__ gamma, const float* __restrict__ beta,
                            float* __restrict__ sc, float* __restrict__ sh, int C) {
    int i = blockIdx.x * blockDim.x + threadIdx.x;
    if (i >= C) return;
    double m = g_sum[i] / (double)Nn;
    double v = g_sq[i] / (double)Nn - m * m;
    float rs = rsqrtf((float)v + 1e-5f);
    float a = gamma[i] * rs;
    sc[i] = a;
    sh[i] = beta[i] - a * (float)m;
}

// h_out = maybe_relu(sc2 * z2 + sh2)
__global__ void bn_apply(const float* __restrict__ Z, float* __restrict__ out, int relu) {
    int i = blockIdx.x * blockDim.x + threadIdx.x;
    if (i >= Nn * EMB) return;
    int col = i % EMB;
    float v = fmaf(g_sc2[col], Z[i], g_sh2[col]);
    if (relu) v = fmaxf(v, 0.0f);
    out[i] = v;
}

// ---------------- launcher -----------------------------------------------------------
extern "C" void kernel_launch(void* const* d_in, const int* in_sizes, int n_in,
                              void* d_out, int out_size) {
    const float* x    = (const float*)d_in[0];
    const float* Wb   = (const float*)d_in[1];
    const float* eps  = (const float*)d_in[2];
    const float* W1   = (const float*)d_in[3];
    const float* b1   = (const float*)d_in[4];
    const float* bn1g = (const float*)d_in[5];
    const float* bn1b = (const float*)d_in[6];
    const float* W2   = (const float*)d_in[7];
    const float* b2   = (const float*)d_in[8];
    const float* bng  = (const float*)d_in[9];
    const float* bnb  = (const float*)d_in[10];
    const int*   ei   = (const int*)d_in[11];
    const int*   ea   = (const int*)d_in[12];
    float* out = (float*)d_out;

    float *hA, *hB, *agg, *z1, *z2, *sc1, *sh1, *sc2, *sh2;
    cudaGetSymbolAddress((void**)&hA,  g_hbufA);
    cudaGetSymbolAddress((void**)&hB,  g_hbufB);
    cudaGetSymbolAddress((void**)&agg, g_agg);
    cudaGetSymbolAddress((void**)&z1,  g_z1);
    cudaGetSymbolAddress((void**)&z2,  g_z2);
    cudaGetSymbolAddress((void**)&sc1, g_sc1);
    cudaGetSymbolAddress((void**)&sh1, g_sh1);
    cudaGetSymbolAddress((void**)&sc2, g_sc2);
    cudaGetSymbolAddress((void**)&sh2, g_sh2);

    const int elems = Nn * EMB;
    const float* hin = x;

    for (int l = 0; l < LAYERS; l++) {
        float* hout = (l == LAYERS - 1) ? out : ((l & 1) ? hB : hA);

        build_etab<<<9, 320>>>(Wb + (size_t)l * EMB * 9);
        agg_init<<<(elems + 255) / 256, 256>>>(hin, eps, l);
        edge_msg<<<(Ee + 7) / 8, 256>>>(hin, ei, ea);

        // GEMM1: z1 = agg @ W1^T + b1   (M=N, NC=600, K=300)
        gemm_tn<0><<<dim3((Nn + 127) / 128, (EMB2 + 63) / 64), 256>>>(
            agg, W1 + (size_t)l * EMB2 * EMB, b1 + (size_t)l * EMB2,
            nullptr, nullptr, z1, Nn, EMB2, EMB);

        zero_stats<<<3, 256>>>(EMB2);
        stats_kernel<<<dim3((EMB2 + 255) / 256, 64), 256>>>(z1, Nn, EMB2);
        bn_finalize<<<3, 256>>>(bn1g + (size_t)l * EMB2, bn1b + (size_t)l * EMB2, sc1, sh1, EMB2);

        // GEMM2: z2 = relu(BN1(z1)) @ W2^T + b2   (M=N, NC=300, K=600), BN1+relu fused
        gemm_tn<1><<<dim3((Nn + 127) / 128, (EMB + 63) / 64), 256>>>(
            z1, W2 + (size_t)l * EMB * EMB2, b2 + (size_t)l * EMB,
            sc1, sh1, z2, Nn, EMB, EMB2);

        zero_stats<<<2, 256>>>(EMB);
        stats_kernel<<<dim3((EMB + 255) / 256, 64), 256>>>(z2, Nn, EMB);
        bn_finalize<<<2, 256>>>(bng + (size_t)l * EMB, bnb + (size_t)l * EMB, sc2, sh2, EMB);

        bn_apply<<<(elems + 255) / 256, 256>>>(z2, hout, (l < LAYERS - 1) ? 1 : 0);

        hin = hout;
    }
}

// round 4
// speedup vs baseline: 1.4765x; 1.4765x over previous
#include <cuda_runtime.h>
#include <cuda_bf16.h>
#include <cstdint>
#include <cstddef>

#define Nn   100000
#define Ee   256000
#define EMB  300
#define EMB2 600
#define LAYERS 5

// GEMM1: A[N,300] * W1[600,300]^T ; K padded to 320 (5 chunks of 64)
// GEMM2: A[N,600] * W2[300,600]^T ; K padded to 640 (10 chunks)
#define KP1 320
#define KP2 640
#define NCH1 5
#define NCH2 10
#define NPAD1 640   // 5 n-tiles of 128
#define NPAD2 384   // 3 n-tiles of 128

// ---------------- device scratch ----------------
__device__ __align__(128) float  g_hbufA[(size_t)Nn * EMB];
__device__ __align__(128) float  g_hbufB[(size_t)Nn * EMB];
__device__ __align__(128) float  g_agg  [(size_t)Nn * EMB];
__device__ __align__(128) float  g_z1   [(size_t)Nn * EMB2];
__device__ __align__(128) float  g_z2   [(size_t)Nn * EMB];
__device__ __align__(128) __nv_bfloat16 g_Ahi[(size_t)Nn * KP2];
__device__ __align__(128) __nv_bfloat16 g_Alo[(size_t)Nn * KP2];
__device__ __align__(128) __nv_bfloat16 g_Bhi[262144];
__device__ __align__(128) __nv_bfloat16 g_Blo[262144];
__device__ float  g_etab [9 * EMB];
__device__ double g_sum  [EMB2];
__device__ double g_sq   [EMB2];
__device__ float  g_sc1  [EMB2];
__device__ float  g_sh1  [EMB2];
__device__ float  g_sc2  [EMB];
__device__ float  g_sh2  [EMB];

// ---------------- PTX helpers (all base sm_80-compatible, no 'a' features) ----------
__device__ __forceinline__ uint32_t smem_u32(const void* p) {
    uint32_t a;
    asm("{ .reg .u64 t; cvta.to.shared.u64 t, %1; cvt.u32.u64 %0, t; }" : "=r"(a) : "l"(p));
    return a;
}
__device__ __forceinline__ void cp_async16(uint32_t dst, const void* src, bool valid) {
    int sz = valid ? 16 : 0;
    asm volatile("cp.async.cg.shared.global [%0], [%1], 16, %2;" :: "r"(dst), "l"(src), "r"(sz));
}
__device__ __forceinline__ void cp_commit() { asm volatile("cp.async.commit_group;"); }
__device__ __forceinline__ uint32_t swz(uint32_t b) { return b ^ ((b >> 3) & 0x70); }

__device__ __forceinline__ void ldsm_x4(uint32_t (&r)[4], uint32_t addr) {
    asm volatile("ldmatrix.sync.aligned.m8n8.x4.shared.b16 {%0,%1,%2,%3}, [%4];"
        : "=r"(r[0]), "=r"(r[1]), "=r"(r[2]), "=r"(r[3]) : "r"(addr));
}
__device__ __forceinline__ void mma16816(float (&d)[4], const uint32_t (&a)[4],
                                         uint32_t b0, uint32_t b1) {
    asm volatile("mma.sync.aligned.m16n8k16.row.col.f32.bf16.bf16.f32 "
        "{%0,%1,%2,%3}, {%4,%5,%6,%7}, {%8,%9}, {%0,%1,%2,%3};"
        : "+f"(d[0]), "+f"(d[1]), "+f"(d[2]), "+f"(d[3])
        : "r"(a[0]), "r"(a[1]), "r"(a[2]), "r"(a[3]), "r"(b0), "r"(b1));
}

// ---------------- graph-side kernels ----------------
__global__ void build_etab(const float* __restrict__ Wb) {
    int c = blockIdx.x, k = threadIdx.x;
    if (k < EMB) g_etab[c * EMB + k] = Wb[k * 9 + c / 3] + Wb[k * 9 + 6 + (c % 3)];
}

__global__ void agg_init(const float* __restrict__ h, const float* __restrict__ eps, int l) {
    int i = blockIdx.x * blockDim.x + threadIdx.x;
    if (i < Nn * EMB) g_agg[i] = (1.0f + __ldg(eps + l)) * h[i];
}

__global__ void edge_msg(const float* __restrict__ h, const int* __restrict__ ei,
                         const int* __restrict__ ea) {
    __shared__ float s_et[9 * EMB];
    for (int i = threadIdx.x; i < 9 * EMB; i += blockDim.x) s_et[i] = g_etab[i];
    __syncthreads();
    int warp = threadIdx.x >> 5, lane = threadIdx.x & 31;
    int e = blockIdx.x * 8 + warp;
    if (e >= Ee) return;
    int src = ei[e], dst = ei[Ee + e];
    int c = ea[2 * e] * 3 + ea[2 * e + 1];
    const float* hr = h + (size_t)src * EMB;
    float* ar = g_agg + (size_t)dst * EMB;
    const float* er = s_et + c * EMB;
    for (int k = lane; k < EMB; k += 32) {
        float v = hr[k] + er[k];
        if (v > 0.0f) atomicAdd(ar + k, v);
    }
}

// split fp32 -> bf16 hi/lo (optionally fused BN1+relu), one row per block
__global__ void split_A(const float* __restrict__ src, int K, int KP,
                        __nv_bfloat16* __restrict__ hi, __nv_bfloat16* __restrict__ lo,
                        const float* __restrict__ sc, const float* __restrict__ sh, int transform) {
    int row = blockIdx.x, col = threadIdx.x;
    float v = 0.0f;
    if (col < K) {
        v = src[(size_t)row * K + col];
        if (transform) v = fmaxf(fmaf(sc[col], v, sh[col]), 0.0f);
    }
    __nv_bfloat16 h = __float2bfloat16_rn(v);
    __nv_bfloat16 l = __float2bfloat16_rn(v - __bfloat162float(h));
    hi[(size_t)row * KP + col] = h;
    lo[(size_t)row * KP + col] = l;
}

__global__ void split_B(const float* __restrict__ W, int NC, int K, int KP) {
    int row = blockIdx.x, col = threadIdx.x;
    float v = (row < NC && col < K) ? W[(size_t)row * K + col] : 0.0f;
    __nv_bfloat16 h = __float2bfloat16_rn(v);
    __nv_bfloat16 l = __float2bfloat16_rn(v - __bfloat162float(h));
    g_Bhi[(size_t)row * KP + col] = h;
    g_Blo[(size_t)row * KP + col] = l;
}

// ---------------- mma.sync split-bf16 GEMM ----------------
// C[M,NC] = Ah*Bh^T + Al*Bh^T + Ah*Bl^T, tile 128x128, K chunk 64 bf16,
// 3-stage cp.async pipeline, 8 warps (2x4), warp tile 64x32, m16n8k16 HMMA.
__global__ void __launch_bounds__(256, 2)
gemm_split(const __nv_bfloat16* __restrict__ Ahi, const __nv_bfloat16* __restrict__ Alo,
           const __nv_bfloat16* __restrict__ Bhi, const __nv_bfloat16* __restrict__ Blo,
           float* __restrict__ C, int M, int NC, int KP, int nch) {
    extern __shared__ __align__(1024) char smem[];
    uint32_t sb = smem_u32(smem);

    int tid = threadIdx.x;
    int wid = tid >> 5, lane = tid & 31;
    int wm = wid >> 2, wn = wid & 3;        // warp grid 2(M) x 4(N)
    int n0 = blockIdx.x * 128;              // n fastest -> A tile L2 reuse
    int m0 = blockIdx.y * 128;
    int niter = 3 * nch;

    int quad = lane >> 3, r = lane & 7;
    int arow_base = wm * 64 + (quad & 1) * 8 + r;        // + mi*16
    int brow_base = wn * 32 + (quad & 1) * 8 + r;        // + nj*16
    int kseg_add = quad >> 1;                            // + ks*2

    float acc[4][4][4];
#pragma unroll
    for (int mi = 0; mi < 4; mi++)
#pragma unroll
        for (int nt = 0; nt < 4; nt++)
#pragma unroll
            for (int q = 0; q < 4; q++) acc[mi][nt][q] = 0.0f;

    auto load_chunk = [&](int c, int buf) {
        int p = c / nch, kc = c - p * nch;
        const __nv_bfloat16* Ab = (p == 1) ? Alo : Ahi;
        const __nv_bfloat16* Bb = (p == 2) ? Blo : Bhi;
        size_t aoff = (size_t)m0 * KP + (size_t)kc * 64;
        size_t boff = (size_t)n0 * KP + (size_t)kc * 64;
        uint32_t sA = sb + buf * 32768;
        uint32_t sB = sA + 16384;
#pragma unroll
        for (int i = 0; i < 4; i++) {
            int seg = tid + i * 256;
            int row = seg >> 3, s = seg & 7;
            uint32_t so = swz(row * 128 + s * 16);
            cp_async16(sA + so, Ab + aoff + (size_t)row * KP + s * 8, (m0 + row) < M);
            cp_async16(sB + so, Bb + boff + (size_t)row * KP + s * 8, true);
        }
        cp_commit();
    };

    load_chunk(0, 0);
    load_chunk(1, 1);

    for (int j = 0; j < niter; j++) {
        if (j + 2 < niter) asm volatile("cp.async.wait_group 1;" ::: "memory");
        else               asm volatile("cp.async.wait_group 0;" ::: "memory");
        __syncthreads();

        if (j + 2 < niter) load_chunk(j + 2, (j + 2) % 3);

        uint32_t sA = sb + (j % 3) * 32768;
        uint32_t sB = sA + 16384;
#pragma unroll
        for (int ks = 0; ks < 4; ks++) {
            int kseg = ks * 2 + kseg_add;
            uint32_t a[4][4];
#pragma unroll
            for (int mi = 0; mi < 4; mi++)
                ldsm_x4(a[mi], sA + swz((arow_base + mi * 16) * 128 + kseg * 16));
            uint32_t b[2][4];
#pragma unroll
            for (int nj = 0; nj < 2; nj++)
                ldsm_x4(b[nj], sB + swz((brow_base + nj * 16) * 128 + kseg * 16));
#pragma unroll
            for (int mi = 0; mi < 4; mi++)
#pragma unroll
                for (int nt = 0; nt < 4; nt++)
                    mma16816(acc[mi][nt], a[mi], b[nt >> 1][nt & 1], b[nt >> 1][(nt & 1) + 2]);
        }
    }

    // ---- epilogue: direct global stores ----
    int rg = lane >> 2, cg = (lane & 3) * 2;
#pragma unroll
    for (int mi = 0; mi < 4; mi++) {
        int r0 = m0 + wm * 64 + mi * 16 + rg;
#pragma unroll
        for (int nt = 0; nt < 4; nt++) {
            int c0 = n0 + wn * 32 + nt * 8 + cg;
            if (c0 < NC) {
                if (r0 < M) {
                    float2 v = make_float2(acc[mi][nt][0], acc[mi][nt][1]);
                    *reinterpret_cast<float2*>(C + (size_t)r0 * NC + c0) = v;
                }
                if (r0 + 8 < M) {
                    float2 v = make_float2(acc[mi][nt][2], acc[mi][nt][3]);
                    *reinterpret_cast<float2*>(C + (size_t)(r0 + 8) * NC + c0) = v;
                }
            }
        }
    }
}

// ---------------- BN helpers ----------------
__global__ void zero_stats(int C) {
    int i = blockIdx.x * blockDim.x + threadIdx.x;
    if (i < C) { g_sum[i] = 0.0; g_sq[i] = 0.0; }
}

__global__ void stats_kernel(const float* __restrict__ Z, int M, int C) {
    int col = blockIdx.x * blockDim.x + threadIdx.x;
    if (col >= C) return;
    int chunk = (M + gridDim.y - 1) / gridDim.y;
    int r0 = blockIdx.y * chunk;
    int r1 = min(M, r0 + chunk);
    float s = 0.f, q = 0.f;
    for (int r = r0; r < r1; r++) {
        float v = Z[(size_t)r * C + col];
        s += v; q += v * v;
    }
    atomicAdd(&g_sum[col], (double)s);
    atomicAdd(&g_sq[col], (double)q);
}

__global__ void bn_finalize(const float* __restrict__ gamma, const float* __restrict__ beta,
                            float* __restrict__ sc, float* __restrict__ sh, int C) {
    int i = blockIdx.x * blockDim.x + threadIdx.x;
    if (i >= C) return;
    double m = g_sum[i] / (double)Nn;
    double v = g_sq[i] / (double)Nn - m * m;
    float rs = rsqrtf((float)v + 1e-5f);
    float a = gamma[i] * rs;
    sc[i] = a;
    sh[i] = beta[i] - a * (float)m;
}

__global__ void bn_apply(const float* __restrict__ Z, float* __restrict__ out, int relu) {
    int i = blockIdx.x * blockDim.x + threadIdx.x;
    if (i >= Nn * EMB) return;
    int col = i % EMB;
    float v = fmaf(g_sc2[col], Z[i], g_sh2[col]);
    if (relu) v = fmaxf(v, 0.0f);
    out[i] = v;
}

// ---------------- launcher ----------------
extern "C" void kernel_launch(void* const* d_in, const int* in_sizes, int n_in,
                              void* d_out, int out_size) {
    const float* x    = (const float*)d_in[0];
    const float* Wb   = (const float*)d_in[1];
    const float* eps  = (const float*)d_in[2];
    const float* W1   = (const float*)d_in[3];
    const float* bn1g = (const float*)d_in[5];
    const float* bn1b = (const float*)d_in[6];
    const float* W2   = (const float*)d_in[7];
    const float* bng  = (const float*)d_in[9];
    const float* bnb  = (const float*)d_in[10];
    const int*   ei   = (const int*)d_in[11];
    const int*   ea   = (const int*)d_in[12];
    float* out = (float*)d_out;

    float *hA, *hB, *agg, *z1, *z2, *sc1, *sh1, *sc2, *sh2;
    __nv_bfloat16 *Ahi, *Alo, *Bhi, *Blo;
    cudaGetSymbolAddress((void**)&hA,  g_hbufA);
    cudaGetSymbolAddress((void**)&hB,  g_hbufB);
    cudaGetSymbolAddress((void**)&agg, g_agg);
    cudaGetSymbolAddress((void**)&z1,  g_z1);
    cudaGetSymbolAddress((void**)&z2,  g_z2);
    cudaGetSymbolAddress((void**)&sc1, g_sc1);
    cudaGetSymbolAddress((void**)&sh1, g_sh1);
    cudaGetSymbolAddress((void**)&sc2, g_sc2);
    cudaGetSymbolAddress((void**)&sh2, g_sh2);
    cudaGetSymbolAddress((void**)&Ahi, g_Ahi);
    cudaGetSymbolAddress((void**)&Alo, g_Alo);
    cudaGetSymbolAddress((void**)&Bhi, g_Bhi);
    cudaGetSymbolAddress((void**)&Blo, g_Blo);

    const int SMEM_BYTES = 3 * 32768;
    cudaFuncSetAttribute(gemm_split, cudaFuncAttributeMaxDynamicSharedMemorySize, SMEM_BYTES);

    const int elems = Nn * EMB;
    const int mtiles = (Nn + 127) / 128;
    const float* hin = x;

    for (int l = 0; l < LAYERS; l++) {
        float* hout = (l == LAYERS - 1) ? out : ((l & 1) ? hB : hA);

        build_etab<<<9, 320>>>(Wb + (size_t)l * EMB * 9);
        agg_init<<<(elems + 255) / 256, 256>>>(hin, eps, l);
        edge_msg<<<(Ee + 7) / 8, 256>>>(hin, ei, ea);

        // ---- GEMM1: z1 = agg @ W1^T (bias dropped: BN shift-invariant) ----
        split_A<<<Nn, KP1>>>(agg, EMB, KP1, Ahi, Alo, nullptr, nullptr, 0);
        split_B<<<NPAD1, KP1>>>(W1 + (size_t)l * EMB2 * EMB, EMB2, EMB, KP1);
        gemm_split<<<dim3(NPAD1 / 128, mtiles), 256, SMEM_BYTES>>>(
            Ahi, Alo, Bhi, Blo, z1, Nn, EMB2, KP1, NCH1);

        zero_stats<<<3, 256>>>(EMB2);
        stats_kernel<<<dim3((EMB2 + 255) / 256, 64), 256>>>(z1, Nn, EMB2);
        bn_finalize<<<3, 256>>>(bn1g + (size_t)l * EMB2, bn1b + (size_t)l * EMB2, sc1, sh1, EMB2);

        // ---- GEMM2: z2 = relu(BN1(z1)) @ W2^T (BN1+relu fused into split) ----
        split_A<<<Nn, KP2>>>(z1, EMB2, KP2, Ahi, Alo, sc1, sh1, 1);
        split_B<<<NPAD2, KP2>>>(W2 + (size_t)l * EMB * EMB2, EMB, EMB2, KP2);
        gemm_split<<<dim3(NPAD2 / 128, mtiles), 256, SMEM_BYTES>>>(
            Ahi, Alo, Bhi, Blo, z2, Nn, EMB, KP2, NCH2);

        zero_stats<<<2, 256>>>(EMB);
        stats_kernel<<<dim3((EMB + 255) / 256, 64), 256>>>(z2, Nn, EMB);
        bn_finalize<<<2, 256>>>(bng + (size_t)l * EMB, bnb + (size_t)l * EMB, sc2, sh2, EMB);

        bn_apply<<<(elems + 255) / 256, 256>>>(z2, hout, (l < LAYERS - 1) ? 1 : 0);

        hin = hout;
    }
}

// round 5
// speedup vs baseline: 1.6541x; 1.1203x over previous
#include <cuda_runtime.h>
#include <cuda_bf16.h>
#include <cstdint>
#include <cstddef>

#define Nn   100000
#define Ee   256000
#define EMB  300
#define EMB2 600
#define LAYERS 5

#define KP1 320
#define KP2 640
#define NCH1 5
#define NCH2 10
#define NPAD1 640   // 5 n-tiles of 128
#define NPAD2 384   // 3 n-tiles of 128

// ---------------- device scratch ----------------
__device__ __align__(128) float  g_hbufA[(size_t)Nn * EMB];
__device__ __align__(128) float  g_hbufB[(size_t)Nn * EMB];
__device__ __align__(128) float  g_agg  [(size_t)Nn * EMB];
__device__ __align__(128) float  g_z1   [(size_t)Nn * EMB2];
__device__ __align__(128) float  g_z2   [(size_t)Nn * EMB];
__device__ __align__(128) __nv_bfloat16 g_Bhi[262144];
__device__ __align__(128) __nv_bfloat16 g_Blo[262144];
__device__ float  g_etab [9 * EMB];
__device__ double g_sum  [EMB2];
__device__ double g_sq   [EMB2];
__device__ float  g_sc1  [EMB2];
__device__ float  g_sh1  [EMB2];
__device__ float  g_sc2  [EMB];
__device__ float  g_sh2  [EMB];

// ---------------- PTX helpers (base sm_80-compatible) ----------------
__device__ __forceinline__ uint32_t smem_u32(const void* p) {
    uint32_t a;
    asm("{ .reg .u64 t; cvta.to.shared.u64 t, %1; cvt.u32.u64 %0, t; }" : "=r"(a) : "l"(p));
    return a;
}
__device__ __forceinline__ void cp_async16(uint32_t dst, const void* src) {
    asm volatile("cp.async.cg.shared.global [%0], [%1], 16;" :: "r"(dst), "l"(src));
}
__device__ __forceinline__ void cp_commit() { asm volatile("cp.async.commit_group;"); }
__device__ __forceinline__ uint32_t swz(uint32_t b) { return b ^ ((b >> 3) & 0x70); }

__device__ __forceinline__ void ldsm_x4(uint32_t (&r)[4], uint32_t addr) {
    asm volatile("ldmatrix.sync.aligned.m8n8.x4.shared.b16 {%0,%1,%2,%3}, [%4];"
        : "=r"(r[0]), "=r"(r[1]), "=r"(r[2]), "=r"(r[3]) : "r"(addr));
}
__device__ __forceinline__ void mma16816(float (&d)[4], const uint32_t (&a)[4],
                                         uint32_t b0, uint32_t b1) {
    asm volatile("mma.sync.aligned.m16n8k16.row.col.f32.bf16.bf16.f32 "
        "{%0,%1,%2,%3}, {%4,%5,%6,%7}, {%8,%9}, {%0,%1,%2,%3};"
        : "+f"(d[0]), "+f"(d[1]), "+f"(d[2]), "+f"(d[3])
        : "r"(a[0]), "r"(a[1]), "r"(a[2]), "r"(a[3]), "r"(b0), "r"(b1));
}
__device__ __forceinline__ void sts64(uint32_t addr, uint32_t a, uint32_t b) {
    asm volatile("st.shared.v2.b32 [%0], {%1,%2};" :: "r"(addr), "r"(a), "r"(b));
}

// ---------------- graph-side kernels ----------------
__global__ void build_etab(const float* __restrict__ Wb) {
    int c = blockIdx.x, k = threadIdx.x;
    if (k < EMB) g_etab[c * EMB + k] = Wb[k * 9 + c / 3] + Wb[k * 9 + 6 + (c % 3)];
}

__global__ void agg_init(const float* __restrict__ h, const float* __restrict__ eps, int l) {
    int i = blockIdx.x * blockDim.x + threadIdx.x;
    if (i < Nn * EMB) g_agg[i] = (1.0f + __ldg(eps + l)) * h[i];
}

__global__ void edge_msg(const float* __restrict__ h, const int* __restrict__ ei,
                         const int* __restrict__ ea) {
    __shared__ float s_et[9 * EMB];
    for (int i = threadIdx.x; i < 9 * EMB; i += blockDim.x) s_et[i] = g_etab[i];
    __syncthreads();
    int warp = threadIdx.x >> 5, lane = threadIdx.x & 31;
    int e = blockIdx.x * 8 + warp;
    if (e >= Ee) return;
    int src = ei[e], dst = ei[Ee + e];
    int c = ea[2 * e] * 3 + ea[2 * e + 1];
    const float* hr = h + (size_t)src * EMB;
    float* ar = g_agg + (size_t)dst * EMB;
    const float* er = s_et + c * EMB;
    for (int k = lane; k < EMB; k += 32) {
        float v = hr[k] + er[k];
        if (v > 0.0f) atomicAdd(ar + k, v);
    }
}

__global__ void split_B(const float* __restrict__ W, int NC, int K, int KP) {
    int row = blockIdx.x, col = threadIdx.x;
    float v = (row < NC && col < K) ? W[(size_t)row * K + col] : 0.0f;
    __nv_bfloat16 h = __float2bfloat16_rn(v);
    __nv_bfloat16 l = __float2bfloat16_rn(v - __bfloat162float(h));
    g_Bhi[(size_t)row * KP + col] = h;
    g_Blo[(size_t)row * KP + col] = l;
}

// ---------------- fused split-bf16 GEMM + on-the-fly convert + stats epilogue ----------
// C[M,NC] = f(A)*Bhi^T (3 phases hh, lh, hl), A loaded fp32 & split in-kernel.
// TRANSFORM: f(x)=relu(sc[k]*x+sh[k]).  Epilogue: C store + column sum/sumsq atomics.
template <int TRANSFORM>
__global__ void __launch_bounds__(256, 1)
gemm_fused(const float* __restrict__ A, float* __restrict__ C,
           const float* __restrict__ sc, const float* __restrict__ sh,
           int M, int NC, int K, int KP, int nch) {
    extern __shared__ __align__(1024) char smem[];
    uint32_t sb = smem_u32(smem);
    // layout: A bufs: sb + buf*32768 (hi @0, lo @16384); B bufs: sb+65536 + buf*32768

    int tid = threadIdx.x;
    int wid = tid >> 5, lane = tid & 31;
    int wm = wid >> 2, wn = wid & 3;        // warp grid 2(M) x 4(N)
    int n0 = blockIdx.x * 128;              // n fastest -> A tile L2 reuse
    int m0 = blockIdx.y * 128;

    int quad = lane >> 3, r = lane & 7;
    int arow_base = wm * 64 + (quad & 1) * 8 + r;
    int brow_base = wn * 32 + (quad & 1) * 8 + r;
    int kseg_add = quad >> 1;

    float acc[4][4][4];
#pragma unroll
    for (int mi = 0; mi < 4; mi++)
#pragma unroll
        for (int nt = 0; nt < 4; nt++)
#pragma unroll
            for (int q = 0; q < 4; q++) acc[mi][nt][q] = 0.0f;

    float4 st[8];   // A staging registers (one 128x64 fp32 chunk / 256 threads)

    auto load_A = [&](int kc) {
#pragma unroll
        for (int i = 0; i < 8; i++) {
            int seg = tid + i * 256;
            int row = seg >> 4, s = seg & 15;
            int gm = m0 + row, gk = kc * 64 + s * 4;
            float4 v = make_float4(0.f, 0.f, 0.f, 0.f);
            if (gm < M && gk < K) {
                v = *reinterpret_cast<const float4*>(A + (size_t)gm * K + gk);
                if (TRANSFORM) {
                    float4 cs = *reinterpret_cast<const float4*>(sc + gk);
                    float4 ds = *reinterpret_cast<const float4*>(sh + gk);
                    v.x = fmaxf(fmaf(cs.x, v.x, ds.x), 0.f);
                    v.y = fmaxf(fmaf(cs.y, v.y, ds.y), 0.f);
                    v.z = fmaxf(fmaf(cs.z, v.z, ds.z), 0.f);
                    v.w = fmaxf(fmaf(cs.w, v.w, ds.w), 0.f);
                }
            }
            st[i] = v;
        }
    };
    auto store_A = [&](int buf) {
        uint32_t sAh = sb + buf * 32768;
#pragma unroll
        for (int i = 0; i < 8; i++) {
            int seg = tid + i * 256;
            int row = seg >> 4, s = seg & 15;
            uint32_t off = swz(row * 128 + s * 8);
            float4 v = st[i];
            __nv_bfloat162 H0 = __floats2bfloat162_rn(v.x, v.y);
            __nv_bfloat162 H1 = __floats2bfloat162_rn(v.z, v.w);
            float rx = v.x - __low2float(H0),  ry = v.y - __high2float(H0);
            float rz = v.z - __low2float(H1),  rw = v.w - __high2float(H1);
            __nv_bfloat162 L0 = __floats2bfloat162_rn(rx, ry);
            __nv_bfloat162 L1 = __floats2bfloat162_rn(rz, rw);
            sts64(sAh + off,         *reinterpret_cast<uint32_t*>(&H0),
                                     *reinterpret_cast<uint32_t*>(&H1));
            sts64(sAh + 16384 + off, *reinterpret_cast<uint32_t*>(&L0),
                                     *reinterpret_cast<uint32_t*>(&L1));
        }
    };
    auto load_B = [&](int kc, int buf) {
        uint32_t sBh = sb + 65536 + buf * 32768;
        size_t boff = (size_t)n0 * KP + (size_t)kc * 64;
#pragma unroll
        for (int i = 0; i < 4; i++) {
            int seg = tid + i * 256;
            int row = seg >> 3, s = seg & 7;
            uint32_t so = swz(row * 128 + s * 16);
            cp_async16(sBh + so,         g_Bhi + boff + (size_t)row * KP + s * 8);
            cp_async16(sBh + 16384 + so, g_Blo + boff + (size_t)row * KP + s * 8);
        }
        cp_commit();
    };

    // prologue: chunk0 into buf0, stage chunk1 in regs
    load_A(0); store_A(0); load_B(0, 0);
    load_A(1);             load_B(1, 1);

    for (int j = 0; j < nch; j++) {
        if (j < nch - 1) asm volatile("cp.async.wait_group 1;" ::: "memory");
        else             asm volatile("cp.async.wait_group 0;" ::: "memory");
        __syncthreads();

        uint32_t bufA = sb + (j & 1) * 32768;
        uint32_t bufB = sb + 65536 + (j & 1) * 32768;
#pragma unroll
        for (int p = 0; p < 3; p++) {
            uint32_t sA = bufA + ((p == 1) ? 16384 : 0);
            uint32_t sB = bufB + ((p == 2) ? 16384 : 0);
#pragma unroll
            for (int ks = 0; ks < 4; ks++) {
                int kseg = ks * 2 + kseg_add;
                uint32_t a[4][4];
#pragma unroll
                for (int mi = 0; mi < 4; mi++)
                    ldsm_x4(a[mi], sA + swz((arow_base + mi * 16) * 128 + kseg * 16));
                uint32_t b[2][4];
#pragma unroll
                for (int nj = 0; nj < 2; nj++)
                    ldsm_x4(b[nj], sB + swz((brow_base + nj * 16) * 128 + kseg * 16));
#pragma unroll
                for (int mi = 0; mi < 4; mi++)
#pragma unroll
                    for (int nt = 0; nt < 4; nt++)
                        mma16816(acc[mi][nt], a[mi], b[nt >> 1][nt & 1], b[nt >> 1][(nt & 1) + 2]);
            }
        }

        if (j + 1 < nch) store_A((j + 1) & 1);   // safe: all warps past MMA on that buf
        if (j + 2 < nch) { load_A(j + 2); load_B(j + 2, j & 1); }
    }

    // ---- epilogue: C stores ----
    int rg = lane >> 2, cg = (lane & 3) * 2;
#pragma unroll
    for (int mi = 0; mi < 4; mi++) {
        int r0 = m0 + wm * 64 + mi * 16 + rg;
#pragma unroll
        for (int nt = 0; nt < 4; nt++) {
            int c0 = n0 + wn * 32 + nt * 8 + cg;
            if (c0 < NC) {
                if (r0 < M)
                    *reinterpret_cast<float2*>(C + (size_t)r0 * NC + c0) =
                        make_float2(acc[mi][nt][0], acc[mi][nt][1]);
                if (r0 + 8 < M)
                    *reinterpret_cast<float2*>(C + (size_t)(r0 + 8) * NC + c0) =
                        make_float2(acc[mi][nt][2], acc[mi][nt][3]);
            }
        }
    }

    // ---- epilogue: fused BN stats (invalid rows are zero-filled => contribute 0) ----
#pragma unroll
    for (int nt = 0; nt < 4; nt++) {
#pragma unroll
        for (int cp = 0; cp < 2; cp++) {
            float s = 0.f, q = 0.f;
#pragma unroll
            for (int mi = 0; mi < 4; mi++) {
                float v0 = acc[mi][nt][cp];
                float v1 = acc[mi][nt][cp + 2];
                s += v0 + v1;
                q += v0 * v0 + v1 * v1;
            }
            // reduce over the 8 lanes sharing this column (lane bits 2..4)
#pragma unroll
            for (int off = 4; off <= 16; off <<= 1) {
                s += __shfl_xor_sync(0xFFFFFFFF, s, off);
                q += __shfl_xor_sync(0xFFFFFFFF, q, off);
            }
            if ((lane >> 2) == 0) {
                int c0 = n0 + wn * 32 + nt * 8 + (lane & 3) * 2 + cp;
                if (c0 < NC) {
                    atomicAdd(&g_sum[c0], (double)s);
                    atomicAdd(&g_sq[c0], (double)q);
                }
            }
        }
    }
}

// ---------------- BN helpers ----------------
__global__ void zero_stats(int C) {
    int i = blockIdx.x * blockDim.x + threadIdx.x;
    if (i < C) { g_sum[i] = 0.0; g_sq[i] = 0.0; }
}

__global__ void bn_finalize(const float* __restrict__ gamma, const float* __restrict__ beta,
                            float* __restrict__ sc, float* __restrict__ sh, int C) {
    int i = blockIdx.x * blockDim.x + threadIdx.x;
    if (i >= C) return;
    double m = g_sum[i] / (double)Nn;
    double v = g_sq[i] / (double)Nn - m * m;
    float rs = rsqrtf((float)v + 1e-5f);
    float a = gamma[i] * rs;
    sc[i] = a;
    sh[i] = beta[i] - a * (float)m;
}

// h = maybe_relu(BN2(z2)); optionally also writes agg=(1+eps[lnext])*h for next layer
__global__ void bn_apply_agg(const float* __restrict__ Z, float* __restrict__ outh,
                             const float* __restrict__ eps, int lnext, int relu, int wagg) {
    int i = blockIdx.x * blockDim.x + threadIdx.x;
    if (i >= Nn * EMB) return;
    int col = i % EMB;
    float v = fmaf(g_sc2[col], Z[i], g_sh2[col]);
    if (relu) v = fmaxf(v, 0.0f);
    outh[i] = v;
    if (wagg) g_agg[i] = (1.0f + __ldg(eps + lnext)) * v;
}

// ---------------- launcher ----------------
extern "C" void kernel_launch(void* const* d_in, const int* in_sizes, int n_in,
                              void* d_out, int out_size) {
    const float* x    = (const float*)d_in[0];
    const float* Wb   = (const float*)d_in[1];
    const float* eps  = (const float*)d_in[2];
    const float* W1   = (const float*)d_in[3];
    const float* bn1g = (const float*)d_in[5];
    const float* bn1b = (const float*)d_in[6];
    const float* W2   = (const float*)d_in[7];
    const float* bng  = (const float*)d_in[9];
    const float* bnb  = (const float*)d_in[10];
    const int*   ei   = (const int*)d_in[11];
    const int*   ea   = (const int*)d_in[12];
    float* out = (float*)d_out;

    float *hA, *hB, *agg, *z1, *z2, *sc1, *sh1, *sc2, *sh2;
    cudaGetSymbolAddress((void**)&hA,  g_hbufA);
    cudaGetSymbolAddress((void**)&hB,  g_hbufB);
    cudaGetSymbolAddress((void**)&agg, g_agg);
    cudaGetSymbolAddress((void**)&z1,  g_z1);
    cudaGetSymbolAddress((void**)&z2,  g_z2);
    cudaGetSymbolAddress((void**)&sc1, g_sc1);
    cudaGetSymbolAddress((void**)&sh1, g_sh1);
    cudaGetSymbolAddress((void**)&sc2, g_sc2);
    cudaGetSymbolAddress((void**)&sh2, g_sh2);

    const int SMEM_BYTES = 131072;  // A 2x32KB + B 2x32KB
    cudaFuncSetAttribute(gemm_fused<0>, cudaFuncAttributeMaxDynamicSharedMemorySize, SMEM_BYTES);
    cudaFuncSetAttribute(gemm_fused<1>, cudaFuncAttributeMaxDynamicSharedMemorySize, SMEM_BYTES);

    const int elems = Nn * EMB;
    const int mtiles = (Nn + 127) / 128;
    const float* hin = x;

    agg_init<<<(elems + 255) / 256, 256>>>(x, eps, 0);

    for (int l = 0; l < LAYERS; l++) {
        float* hout = (l == LAYERS - 1) ? out : ((l & 1) ? hB : hA);

        build_etab<<<9, 320>>>(Wb + (size_t)l * EMB * 9);
        edge_msg<<<(Ee + 7) / 8, 256>>>(hin, ei, ea);

        // ---- GEMM1: z1 = agg @ W1^T  (stats fused; bias dropped: BN shift-invariant)
        split_B<<<NPAD1, KP1>>>(W1 + (size_t)l * EMB2 * EMB, EMB2, EMB, KP1);
        zero_stats<<<3, 256>>>(EMB2);
        gemm_fused<0><<<dim3(NPAD1 / 128, mtiles), 256, SMEM_BYTES>>>(
            agg, z1, nullptr, nullptr, Nn, EMB2, EMB, KP1, NCH1);
        bn_finalize<<<3, 256>>>(bn1g + (size_t)l * EMB2, bn1b + (size_t)l * EMB2, sc1, sh1, EMB2);

        // ---- GEMM2: z2 = relu(BN1(z1)) @ W2^T  (BN1+relu in A-load; stats fused)
        split_B<<<NPAD2, KP2>>>(W2 + (size_t)l * EMB * EMB2, EMB, EMB2, KP2);
        zero_stats<<<2, 256>>>(EMB);
        gemm_fused<1><<<dim3(NPAD2 / 128, mtiles), 256, SMEM_BYTES>>>(
            z1, z2, sc1, sh1, Nn, EMB, EMB2, KP2, NCH2);
        bn_finalize<<<2, 256>>>(bng + (size_t)l * EMB, bnb + (size_t)l * EMB, sc2, sh2, EMB);

        // ---- BN2 apply (+relu) fused with next layer's agg init
        bn_apply_agg<<<(elems + 255) / 256, 256>>>(z2, hout, eps,
                                                   (l < LAYERS - 1) ? l + 1 : 0,
                                                   (l < LAYERS - 1) ? 1 : 0,
                                                   (l < LAYERS - 1) ? 1 : 0);
        hin = hout;
    }
}

// round 9
// speedup vs baseline: 1.7500x; 1.0580x over previous
#include <cuda_runtime.h>
#include <cuda_bf16.h>
#include <cstdint>
#include <cstddef>

#define Nn   100000
#define Ee   256000
#define EMB  300
#define EMB2 600
#define LAYERS 5

#define KP1 320
#define KP2 640
#define NCH1 5
#define NCH2 10
#define NPAD1 640   // 5 n-tiles of 128
#define NPAD2 384   // 3 n-tiles of 128

// ---------------- device scratch ----------------
__device__ __align__(128) float  g_hbufA[(size_t)Nn * EMB];
__device__ __align__(128) float  g_hbufB[(size_t)Nn * EMB];
__device__ __align__(128) float  g_agg  [(size_t)Nn * EMB];
__device__ __align__(128) float  g_z1   [(size_t)Nn * EMB2];
__device__ __align__(128) float  g_z2   [(size_t)Nn * EMB];
__device__ __align__(128) __nv_bfloat16 g_Bhi[262144];
__device__ __align__(128) __nv_bfloat16 g_Blo[262144];
__device__ __align__(16) float g_etab [9 * EMB];
__device__ double g_sum  [EMB2];
__device__ double g_sq   [EMB2];
__device__ float  g_sc1  [EMB2];
__device__ float  g_sh1  [EMB2];
__device__ float  g_sc2  [EMB];
__device__ float  g_sh2  [EMB];

// ---------------- PTX helpers ----------------
__device__ __forceinline__ uint32_t smem_u32(const void* p) {
    uint32_t a;
    asm("{ .reg .u64 t; cvta.to.shared.u64 t, %1; cvt.u32.u64 %0, t; }" : "=r"(a) : "l"(p));
    return a;
}
__device__ __forceinline__ void cp_async16(uint32_t dst, const void* src) {
    asm volatile("cp.async.cg.shared.global [%0], [%1], 16;" :: "r"(dst), "l"(src));
}
__device__ __forceinline__ void cp_commit() { asm volatile("cp.async.commit_group;"); }
__device__ __forceinline__ uint32_t swz(uint32_t b) { return b ^ ((b >> 3) & 0x70); }

__device__ __forceinline__ void ldsm_x4(uint32_t (&r)[4], uint32_t addr) {
    asm volatile("ldmatrix.sync.aligned.m8n8.x4.shared.b16 {%0,%1,%2,%3}, [%4];"
        : "=r"(r[0]), "=r"(r[1]), "=r"(r[2]), "=r"(r[3]) : "r"(addr));
}
__device__ __forceinline__ void mma16816(float (&d)[4], const uint32_t (&a)[4],
                                         uint32_t b0, uint32_t b1) {
    asm volatile("mma.sync.aligned.m16n8k16.row.col.f32.bf16.bf16.f32 "
        "{%0,%1,%2,%3}, {%4,%5,%6,%7}, {%8,%9}, {%0,%1,%2,%3};"
        : "+f"(d[0]), "+f"(d[1]), "+f"(d[2]), "+f"(d[3])
        : "r"(a[0]), "r"(a[1]), "r"(a[2]), "r"(a[3]), "r"(b0), "r"(b1));
}
__device__ __forceinline__ void sts64(uint32_t addr, uint32_t a, uint32_t b) {
    asm volatile("st.shared.v2.b32 [%0], {%1,%2};" :: "r"(addr), "r"(a), "r"(b));
}
__device__ __forceinline__ void red_add_v4(float* addr, float a, float b, float c, float d) {
    asm volatile("red.global.add.v4.f32 [%0], {%1,%2,%3,%4};"
        :: "l"(addr), "f"(a), "f"(b), "f"(c), "f"(d) : "memory");
}

// ---------------- elementwise / prep kernels ----------------
__global__ void agg_init(const float* __restrict__ h, const float* __restrict__ eps, int l) {
    int i = blockIdx.x * blockDim.x + threadIdx.x;
    if (i < Nn * EMB) g_agg[i] = (1.0f + __ldg(eps + l)) * h[i];
}

// prep1: split W1 -> Bhi/Blo (blocks 0..639), build etab (640..648), zero stats600 (649)
// (zeroing here is safe: previous consumer of stats600 ran in an earlier launch)
__global__ void prep1(const float* __restrict__ W1, const float* __restrict__ Wb) {
    int b = blockIdx.x, t = threadIdx.x;
    if (b < NPAD1) {
        float v = (b < EMB2 && t < EMB) ? W1[(size_t)b * EMB + t] : 0.0f;
        __nv_bfloat16 h = __float2bfloat16_rn(v);
        g_Bhi[(size_t)b * KP1 + t] = h;
        g_Blo[(size_t)b * KP1 + t] = __float2bfloat16_rn(v - __bfloat162float(h));
    } else if (b < NPAD1 + 9) {
        int c = b - NPAD1;
        if (t < EMB) g_etab[c * EMB + t] = Wb[t * 9 + c / 3] + Wb[t * 9 + 6 + (c % 3)];
    } else {
        for (int i = t; i < EMB2; i += blockDim.x) { g_sum[i] = 0.0; g_sq[i] = 0.0; }
    }
}

// prep2: split W2 (blocks 0..383); block 384: BN1 finalize THEN zero stats300
// (finalize and zeroing must be in the SAME block, ordered by __syncthreads —
//  a separate zeroing block races with the finalize reads. That race was R6's bug.)
__global__ void prep2(const float* __restrict__ W2,
                      const float* __restrict__ gamma, const float* __restrict__ beta) {
    int b = blockIdx.x, t = threadIdx.x;
    if (b < NPAD2) {
        for (int c = t; c < KP2; c += blockDim.x) {
            float v = (b < EMB && c < EMB2) ? W2[(size_t)b * EMB2 + c] : 0.0f;
            __nv_bfloat16 h = __float2bfloat16_rn(v);
            g_Bhi[(size_t)b * KP2 + c] = h;
            g_Blo[(size_t)b * KP2 + c] = __float2bfloat16_rn(v - __bfloat162float(h));
        }
    } else {
        for (int i = t; i < EMB2; i += blockDim.x) {
            double m = g_sum[i] / (double)Nn;
            double v = g_sq[i] / (double)Nn - m * m;
            float rs = rsqrtf((float)v + 1e-5f);
            float a = gamma[i] * rs;
            g_sc1[i] = a;
            g_sh1[i] = beta[i] - a * (float)m;
        }
        __syncthreads();
        for (int i = t; i < EMB; i += blockDim.x) { g_sum[i] = 0.0; g_sq[i] = 0.0; }
    }
}

__global__ void bn_finalize2(const float* __restrict__ gamma, const float* __restrict__ beta) {
    int i = blockIdx.x * blockDim.x + threadIdx.x;
    if (i >= EMB) return;
    double m = g_sum[i] / (double)Nn;
    double v = g_sq[i] / (double)Nn - m * m;
    float rs = rsqrtf((float)v + 1e-5f);
    float a = gamma[i] * rs;
    g_sc2[i] = a;
    g_sh2[i] = beta[i] - a * (float)m;
}

// h = maybe_relu(BN2(z2)); optionally also writes agg=(1+eps[lnext])*h
__global__ void bn_apply_agg(const float* __restrict__ Z, float* __restrict__ outh,
                             const float* __restrict__ eps, int lnext, int relu, int wagg) {
    int i = blockIdx.x * blockDim.x + threadIdx.x;
    if (i >= Nn * EMB) return;
    int col = i % EMB;
    float v = fmaf(g_sc2[col], Z[i], g_sh2[col]);
    if (relu) v = fmaxf(v, 0.0f);
    outh[i] = v;
    if (wagg) g_agg[i] = (1.0f + __ldg(eps + lnext)) * v;
}

// ---------------- edge scatter: 64 edges / 256-thread block, float4 + vector RED ------
#define EDGES_PER_BLOCK 64
__global__ void __launch_bounds__(256)
edge_msg(const float* __restrict__ h, const int* __restrict__ ei,
         const int* __restrict__ ea) {
    __shared__ __align__(16) float s_et[9 * EMB];
    for (int i = threadIdx.x; i < 9 * EMB; i += blockDim.x) s_et[i] = g_etab[i];
    __syncthreads();

    int warp = threadIdx.x >> 5, lane = threadIdx.x & 31;
    int ebase = blockIdx.x * EDGES_PER_BLOCK + warp * (EDGES_PER_BLOCK / 8);

#pragma unroll
    for (int u = 0; u < EDGES_PER_BLOCK / 8; u++) {
        int e = ebase + u;
        if (e >= Ee) return;
        int src = __ldg(ei + e);
        int dst = __ldg(ei + Ee + e);
        int c   = __ldg(ea + 2 * e) * 3 + __ldg(ea + 2 * e + 1);

        const float4* hr = reinterpret_cast<const float4*>(h + (size_t)src * EMB);
        float*        ar = g_agg + (size_t)dst * EMB;
        const float4* er = reinterpret_cast<const float4*>(s_et + c * EMB);

#pragma unroll
        for (int it = 0; it < 3; it++) {
            int k = lane + it * 32;
            if (k < 75) {
                float4 hv = __ldg(hr + k);
                float4 ev = er[k];
                float a = fmaxf(hv.x + ev.x, 0.0f);
                float b = fmaxf(hv.y + ev.y, 0.0f);
                float cc = fmaxf(hv.z + ev.z, 0.0f);
                float d = fmaxf(hv.w + ev.w, 0.0f);
                if (a + b + cc + d > 0.0f)
                    red_add_v4(ar + k * 4, a, b, cc, d);
            }
        }
    }
}

// ---------------- fused split-bf16 GEMM + stats epilogue ----------------
template <int TRANSFORM>
__global__ void __launch_bounds__(256, 1)
gemm_fused(const float* __restrict__ A, float* __restrict__ C,
           const float* __restrict__ sc, const float* __restrict__ sh,
           int M, int NC, int K, int KP, int nch) {
    extern __shared__ __align__(1024) char smem[];
    uint32_t sb = smem_u32(smem);

    int tid = threadIdx.x;
    int wid = tid >> 5, lane = tid & 31;
    int wm = wid >> 2, wn = wid & 3;
    int n0 = blockIdx.x * 128;
    int m0 = blockIdx.y * 128;

    int quad = lane >> 3, r = lane & 7;
    int arow_base = wm * 64 + (quad & 1) * 8 + r;
    int brow_base = wn * 32 + (quad & 1) * 8 + r;
    int kseg_add = quad >> 1;

    float acc[4][4][4];
#pragma unroll
    for (int mi = 0; mi < 4; mi++)
#pragma unroll
        for (int nt = 0; nt < 4; nt++)
#pragma unroll
            for (int q = 0; q < 4; q++) acc[mi][nt][q] = 0.0f;

    float4 st[8];

    auto load_A = [&](int kc) {
#pragma unroll
        for (int i = 0; i < 8; i++) {
            int seg = tid + i * 256;
            int row = seg >> 4, s = seg & 15;
            int gm = m0 + row, gk = kc * 64 + s * 4;
            float4 v = make_float4(0.f, 0.f, 0.f, 0.f);
            if (gm < M && gk < K) {
                v = *reinterpret_cast<const float4*>(A + (size_t)gm * K + gk);
                if (TRANSFORM) {
                    float4 cs = *reinterpret_cast<const float4*>(sc + gk);
                    float4 ds = *reinterpret_cast<const float4*>(sh + gk);
                    v.x = fmaxf(fmaf(cs.x, v.x, ds.x), 0.f);
                    v.y = fmaxf(fmaf(cs.y, v.y, ds.y), 0.f);
                    v.z = fmaxf(fmaf(cs.z, v.z, ds.z), 0.f);
                    v.w = fmaxf(fmaf(cs.w, v.w, ds.w), 0.f);
                }
            }
            st[i] = v;
        }
    };
    auto store_A = [&](int buf) {
        uint32_t sAh = sb + buf * 32768;
#pragma unroll
        for (int i = 0; i < 8; i++) {
            int seg = tid + i * 256;
            int row = seg >> 4, s = seg & 15;
            uint32_t off = swz(row * 128 + s * 8);
            float4 v = st[i];
            __nv_bfloat162 H0 = __floats2bfloat162_rn(v.x, v.y);
            __nv_bfloat162 H1 = __floats2bfloat162_rn(v.z, v.w);
            float rx = v.x - __low2float(H0),  ry = v.y - __high2float(H0);
            float rz = v.z - __low2float(H1),  rw = v.w - __high2float(H1);
            __nv_bfloat162 L0 = __floats2bfloat162_rn(rx, ry);
            __nv_bfloat162 L1 = __floats2bfloat162_rn(rz, rw);
            sts64(sAh + off,         *reinterpret_cast<uint32_t*>(&H0),
                                     *reinterpret_cast<uint32_t*>(&H1));
            sts64(sAh + 16384 + off, *reinterpret_cast<uint32_t*>(&L0),
                                     *reinterpret_cast<uint32_t*>(&L1));
        }
    };
    auto load_B = [&](int kc, int buf) {
        uint32_t sBh = sb + 65536 + buf * 32768;
        size_t boff = (size_t)n0 * KP + (size_t)kc * 64;
#pragma unroll
        for (int i = 0; i < 4; i++) {
            int seg = tid + i * 256;
            int row = seg >> 3, s = seg & 7;
            uint32_t so = swz(row * 128 + s * 16);
            cp_async16(sBh + so,         g_Bhi + boff + (size_t)row * KP + s * 8);
            cp_async16(sBh + 16384 + so, g_Blo + boff + (size_t)row * KP + s * 8);
        }
        cp_commit();
    };

    load_A(0); store_A(0); load_B(0, 0);
    load_A(1);             load_B(1, 1);

    for (int j = 0; j < nch; j++) {
        if (j < nch - 1) asm volatile("cp.async.wait_group 1;" ::: "memory");
        else             asm volatile("cp.async.wait_group 0;" ::: "memory");
        __syncthreads();

        uint32_t bufA = sb + (j & 1) * 32768;
        uint32_t bufB = sb + 65536 + (j & 1) * 32768;
#pragma unroll
        for (int p = 0; p < 3; p++) {
            uint32_t sA = bufA + ((p == 1) ? 16384 : 0);
            uint32_t sB = bufB + ((p == 2) ? 16384 : 0);
#pragma unroll
            for (int ks = 0; ks < 4; ks++) {
                int kseg = ks * 2 + kseg_add;
                uint32_t a[4][4];
#pragma unroll
                for (int mi = 0; mi < 4; mi++)
                    ldsm_x4(a[mi], sA + swz((arow_base + mi * 16) * 128 + kseg * 16));
                uint32_t b[2][4];
#pragma unroll
                for (int nj = 0; nj < 2; nj++)
                    ldsm_x4(b[nj], sB + swz((brow_base + nj * 16) * 128 + kseg * 16));
#pragma unroll
                for (int mi = 0; mi < 4; mi++)
#pragma unroll
                    for (int nt = 0; nt < 4; nt++)
                        mma16816(acc[mi][nt], a[mi], b[nt >> 1][nt & 1], b[nt >> 1][(nt & 1) + 2]);
            }
        }

        if (j + 1 < nch) store_A((j + 1) & 1);
        if (j + 2 < nch) { load_A(j + 2); load_B(j + 2, j & 1); }
    }

    int rg = lane >> 2, cg = (lane & 3) * 2;
#pragma unroll
    for (int mi = 0; mi < 4; mi++) {
        int r0 = m0 + wm * 64 + mi * 16 + rg;
#pragma unroll
        for (int nt = 0; nt < 4; nt++) {
            int c0 = n0 + wn * 32 + nt * 8 + cg;
            if (c0 < NC) {
                if (r0 < M)
                    *reinterpret_cast<float2*>(C + (size_t)r0 * NC + c0) =
                        make_float2(acc[mi][nt][0], acc[mi][nt][1]);
                if (r0 + 8 < M)
                    *reinterpret_cast<float2*>(C + (size_t)(r0 + 8) * NC + c0) =
                        make_float2(acc[mi][nt][2], acc[mi][nt][3]);
            }
        }
    }

#pragma unroll
    for (int nt = 0; nt < 4; nt++) {
#pragma unroll
        for (int cp = 0; cp < 2; cp++) {
            float s = 0.f, q = 0.f;
#pragma unroll
            for (int mi = 0; mi < 4; mi++) {
                float v0 = acc[mi][nt][cp];
                float v1 = acc[mi][nt][cp + 2];
                s += v0 + v1;
                q += v0 * v0 + v1 * v1;
            }
#pragma unroll
            for (int off = 4; off <= 16; off <<= 1) {
                s += __shfl_xor_sync(0xFFFFFFFF, s, off);
                q += __shfl_xor_sync(0xFFFFFFFF, q, off);
            }
            if ((lane >> 2) == 0) {
                int c0 = n0 + wn * 32 + nt * 8 + (lane & 3) * 2 + cp;
                if (c0 < NC) {
                    atomicAdd(&g_sum[c0], (double)s);
                    atomicAdd(&g_sq[c0], (double)q);
                }
            }
        }
    }
}

// ---------------- launcher ----------------
extern "C" void kernel_launch(void* const* d_in, const int* in_sizes, int n_in,
                              void* d_out, int out_size) {
    const float* x    = (const float*)d_in[0];
    const float* Wb   = (const float*)d_in[1];
    const float* eps  = (const float*)d_in[2];
    const float* W1   = (const float*)d_in[3];
    const float* bn1g = (const float*)d_in[5];
    const float* bn1b = (const float*)d_in[6];
    const float* W2   = (const float*)d_in[7];
    const float* bng  = (const float*)d_in[9];
    const float* bnb  = (const float*)d_in[10];
    const int*   ei   = (const int*)d_in[11];
    const int*   ea   = (const int*)d_in[12];
    float* out = (float*)d_out;

    float *hA, *hB, *agg, *z1, *z2, *sc1, *sh1;
    cudaGetSymbolAddress((void**)&hA,  g_hbufA);
    cudaGetSymbolAddress((void**)&hB,  g_hbufB);
    cudaGetSymbolAddress((void**)&agg, g_agg);
    cudaGetSymbolAddress((void**)&z1,  g_z1);
    cudaGetSymbolAddress((void**)&z2,  g_z2);
    cudaGetSymbolAddress((void**)&sc1, g_sc1);
    cudaGetSymbolAddress((void**)&sh1, g_sh1);

    const int SMEM_BYTES = 131072;
    cudaFuncSetAttribute(gemm_fused<0>, cudaFuncAttributeMaxDynamicSharedMemorySize, SMEM_BYTES);
    cudaFuncSetAttribute(gemm_fused<1>, cudaFuncAttributeMaxDynamicSharedMemorySize, SMEM_BYTES);

    const int elems = Nn * EMB;
    const int mtiles = (Nn + 127) / 128;
    const float* hin = x;

    agg_init<<<(elems + 255) / 256, 256>>>(x, eps, 0);

    for (int l = 0; l < LAYERS; l++) {
        float* hout = (l == LAYERS - 1) ? out : ((l & 1) ? hB : hA);

        // prep1: W1 split + etab + zero stats600
        prep1<<<NPAD1 + 10, 320>>>(W1 + (size_t)l * EMB2 * EMB, Wb + (size_t)l * EMB * 9);

        edge_msg<<<(Ee + EDGES_PER_BLOCK - 1) / EDGES_PER_BLOCK, 256>>>(hin, ei, ea);

        // GEMM1: z1 = agg @ W1^T  (stats fused)
        gemm_fused<0><<<dim3(NPAD1 / 128, mtiles), 256, SMEM_BYTES>>>(
            agg, z1, nullptr, nullptr, Nn, EMB2, EMB, KP1, NCH1);

        // prep2: W2 split + BN1 finalize + (ordered) zero stats300
        prep2<<<NPAD2 + 1, 320>>>(W2 + (size_t)l * EMB * EMB2,
                                  bn1g + (size_t)l * EMB2, bn1b + (size_t)l * EMB2);

        // GEMM2: z2 = relu(BN1(z1)) @ W2^T  (BN1+relu in A-load; stats fused)
        gemm_fused<1><<<dim3(NPAD2 / 128, mtiles), 256, SMEM_BYTES>>>(
            z1, z2, sc1, sh1, Nn, EMB, EMB2, KP2, NCH2);

        bn_finalize2<<<1, 320>>>(bng + (size_t)l * EMB, bnb + (size_t)l * EMB);

        bn_apply_agg<<<(elems + 255) / 256, 256>>>(z2, hout, eps,
                                                   (l < LAYERS - 1) ? l + 1 : 0,
                                                   (l < LAYERS - 1) ? 1 : 0,
                                                   (l < LAYERS - 1) ? 1 : 0);
        hin = hout;
    }
}